// round 5
// baseline (speedup 1.0000x reference)
#include <cuda_runtime.h>
#include <math.h>

// Fixed problem shapes
#define TT 32      // T
#define NN 8       // neighbors
#define DD 64      // embedding dim
#define NRR 32     // num relations

// ---------------------------------------------------------------------------
// Single fused kernel. Block = batch index b (512 blocks, 256 threads).
//   warps 0-3: user side   (64 units = L*T, 16 per warp)
//   warps 4-7: item side
// Attention logit folded: pi = e_h.w1 + rdot[r] + e_t.w3, where
//   w_k = W @ a_k   and   rdot[r] = dot(R[r], w2)  (precomputed per block).
// Phase A (per 4-unit batch): gather + attention -> x into sX.
// Phase B: batched matvec, d unrolled by 4 with float4 x broadcasts.
// ---------------------------------------------------------------------------
__global__ __launch_bounds__(256, 5) void ckgat_fused(
    const int* __restrict__ items,
    const int* __restrict__ user_h,  const int* __restrict__ user_t,
    const int* __restrict__ user_nh, const int* __restrict__ user_nr, const int* __restrict__ user_nt,
    const int* __restrict__ item_h,  const int* __restrict__ item_t,
    const int* __restrict__ item_nh, const int* __restrict__ item_nr, const int* __restrict__ item_nt,
    const float* __restrict__ E,     // entity_emb [NE,64]
    const float* __restrict__ R,     // relation_emb [32,64]
    const float* __restrict__ W,     // W_GAT [64,64]
    const float* __restrict__ aG,    // a_GAT [3*64]
    float* __restrict__ out,
    int B, int L)
{
    __shared__ float  sW[DD * DD];       // 16 KB
    __shared__ float  sw[3 * DD];        // folded W@a slices, 768 B
    __shared__ float  srd[NRR];          // rdot per relation, 128 B
    __shared__ float4 sX[8][4][DD / 4];  // warp, slot, dim/4: 8 KB
    __shared__ float2 sAcc[8][32];       // 2 KB

    const int tid  = threadIdx.x;
    const int lane = tid & 31;
    const int warp = tid >> 5;
    const int side = warp >> 2;          // 0 = user, 1 = item
    const int wu   = warp & 3;           // warp-in-side
    const int b    = blockIdx.x;

    // Stage W; fold w_k[d] = sum_j W[d][j]*a[k*64+j]
    for (int i = tid; i < DD * DD; i += 256) sW[i] = W[i];
    if (tid < DD) {
        float s0 = 0.f, s1 = 0.f, s2 = 0.f;
        #pragma unroll 8
        for (int j = 0; j < DD; j++) {
            float w = W[tid * DD + j];
            s0 += w * aG[j];
            s1 += w * aG[DD + j];
            s2 += w * aG[2 * DD + j];
        }
        sw[tid] = s0; sw[DD + tid] = s1; sw[2 * DD + tid] = s2;
    }
    __syncthreads();
    // rdot[r] = dot(R[r], w2)  (32 relations, one thread each)
    if (tid < NRR) {
        float s = 0.f;
        #pragma unroll 8
        for (int d = 0; d < DD; d++) s += R[tid * DD + d] * sw[DD + d];
        srd[tid] = s;
    }
    __syncthreads();

    // Per-lane slices of folded vectors: dims {2*lane, 2*lane+1}
    const float2 w1 = *(const float2*)&sw[2 * lane];
    const float2 w3 = *(const float2*)&sw[2 * DD + 2 * lane];

    const int* nhp = side ? item_nh : user_nh;
    const int* nrp = side ? item_nr : user_nr;
    const int* ntp = side ? item_nt : user_nt;
    const int* tp  = side ? item_t  : user_t;

    float2 acc = make_float2(0.f, 0.f);

    const int nUnits  = L * TT;              // 64 for L=2
    const int perWarp = nUnits / 4;          // 16
    const int nBatch  = (perWarp + 3) / 4;   // 4

    for (int jb = 0; jb < nBatch; jb++) {
        const int nIn = (perWarp - jb * 4) < 4 ? (perWarp - jb * 4) : 4;

        // -------- Phase A: attention for nIn units; x -> sX --------
        for (int i = 0; i < nIn; i++) {
            const int u = wu + 4 * (jb * 4 + i);   // unit id, unique over warps-in-side
            const int l = u >> 5;                  // layer (T=32)
            const int t = u & 31;
            const long b3 = ((long)l * B + b) * TT + t;
            const long b4 = b3 * NN;

            // Front-batch neighbor indices (contiguous, N=8 innermost)
            const int4 nh0 = *(const int4*)&nhp[b4];
            const int4 nh1 = *(const int4*)&nhp[b4 + 4];
            const int4 nt0 = *(const int4*)&ntp[b4];
            const int4 nt1 = *(const int4*)&ntp[b4 + 4];
            const int4 nr0 = *(const int4*)&nrp[b4];
            const int4 nr1 = *(const int4*)&nrp[b4 + 4];
            const int hidx[NN] = {nh0.x, nh0.y, nh0.z, nh0.w, nh1.x, nh1.y, nh1.z, nh1.w};
            const int tidx[NN] = {nt0.x, nt0.y, nt0.z, nt0.w, nt1.x, nt1.y, nt1.z, nt1.w};
            const int ridx[NN] = {nr0.x, nr0.y, nr0.z, nr0.w, nr1.x, nr1.y, nr1.z, nr1.w};

            float2 eh[NN];
            float  pp[NN];
            #pragma unroll
            for (int n = 0; n < NN; n++) {
                float2 e  = *(const float2*)&E[(long)hidx[n] * DD + 2 * lane];
                float2 et = *(const float2*)&E[(long)tidx[n] * DD + 2 * lane];
                eh[n] = e;
                pp[n] = e.x * w1.x + e.y * w1.y
                      + et.x * w3.x + et.y * w3.y;
            }
            #pragma unroll
            for (int n = 0; n < NN; n++) {
                #pragma unroll
                for (int off = 16; off; off >>= 1)
                    pp[n] += __shfl_xor_sync(0xffffffffu, pp[n], off);
            }
            // add relation term, leaky relu, softmax over 8 (redundant per lane)
            float m = -1e30f;
            #pragma unroll
            for (int n = 0; n < NN; n++) {
                float p = pp[n] + srd[ridx[n]];
                p = p > 0.f ? p : 0.2f * p;
                pp[n] = p;
                m = fmaxf(m, p);
            }
            float s = 0.f;
            #pragma unroll
            for (int n = 0; n < NN; n++) { pp[n] = __expf(pp[n] - m); s += pp[n]; }
            const float inv = 1.f / s;

            const int tix = tp[b3];
            float2 x = *(const float2*)&E[(long)tix * DD + 2 * lane];
            #pragma unroll
            for (int n = 0; n < NN; n++) {
                const float a_ = pp[n] * inv;
                x.x += a_ * eh[n].x;
                x.y += a_ * eh[n].y;
            }
            ((float2*)&sX[warp][i][0])[lane] = x;
        }
        __syncwarp();

        // -------- Phase B: batched matvec y_i = elu(x_i @ W) --------
        const float2* sW2 = (const float2*)sW;   // sW2[d*32 + lane]
        float2 y[4];
        #pragma unroll
        for (int i = 0; i < 4; i++) y[i] = make_float2(0.f, 0.f);
        #pragma unroll 4
        for (int d4 = 0; d4 < DD / 4; d4++) {
            const float2 wr0 = sW2[(d4 * 4 + 0) * 32 + lane];
            const float2 wr1 = sW2[(d4 * 4 + 1) * 32 + lane];
            const float2 wr2 = sW2[(d4 * 4 + 2) * 32 + lane];
            const float2 wr3 = sW2[(d4 * 4 + 3) * 32 + lane];
            #pragma unroll
            for (int i = 0; i < 4; i++) {
                const float4 xv = sX[warp][i][d4];   // broadcast
                y[i].x += xv.x * wr0.x + xv.y * wr1.x + xv.z * wr2.x + xv.w * wr3.x;
                y[i].y += xv.x * wr0.y + xv.y * wr1.y + xv.z * wr2.y + xv.w * wr3.y;
            }
        }
        for (int i = 0; i < nIn; i++) {
            float y0 = y[i].x, y1 = y[i].y;
            y0 = y0 > 0.f ? y0 : (__expf(y0) - 1.f);
            y1 = y1 > 0.f ? y1 : (__expf(y1) - 1.f);
            acc.x += y0;
            acc.y += y1;
        }
        __syncwarp();
    }

    // Base term: mean over T of E[h0[b][t]]; each warp-in-side takes 8 t's
    {
        const int* hp = side ? item_h : user_h;
        const float sc = 1.f / (float)TT;
        for (int t = wu * 8; t < wu * 8 + 8; t++) {
            int hi = hp[(long)b * TT + t];
            float2 e = *(const float2*)&E[(long)hi * DD + 2 * lane];
            acc.x += e.x * sc;
            acc.y += e.y * sc;
        }
    }
    // Item-side extra: E[items[b]]
    if (side == 1 && wu == 0) {
        int ii = items[b];
        float2 e = *(const float2*)&E[(long)ii * DD + 2 * lane];
        acc.x += e.x;
        acc.y += e.y;
    }

    sAcc[warp][lane] = acc;
    __syncthreads();

    // Warp 0: reduce both sides, dot, sigmoid, write
    if (warp == 0) {
        float2 u = sAcc[0][lane];
        float2 v = sAcc[4][lane];
        #pragma unroll
        for (int w = 1; w < 4; w++) {
            u.x += sAcc[w][lane].x;     u.y += sAcc[w][lane].y;
            v.x += sAcc[4 + w][lane].x; v.y += sAcc[4 + w][lane].y;
        }
        float d = u.x * v.x + u.y * v.y;
        #pragma unroll
        for (int off = 16; off; off >>= 1)
            d += __shfl_xor_sync(0xffffffffu, d, off);
        if (lane == 0) out[b] = 1.f / (1.f + __expf(-d));
    }
}

// ---------------------------------------------------------------------------
// launch. Inputs (metadata order):
//  0 items, 1 user_h, 2 user_r, 3 user_t, 4 user_nh, 5 user_nr, 6 user_nt,
//  7 item_h, 8 item_r, 9 item_t, 10 item_nh, 11 item_nr, 12 item_nt,
//  13 entity_emb, 14 relation_emb, 15 W_GAT, 16 a_GAT
// ---------------------------------------------------------------------------
extern "C" void kernel_launch(void* const* d_in, const int* in_sizes, int n_in,
                              void* d_out, int out_size) {
    const int*   items   = (const int*)d_in[0];
    const int*   user_h  = (const int*)d_in[1];
    const int*   user_t  = (const int*)d_in[3];
    const int*   user_nh = (const int*)d_in[4];
    const int*   user_nr = (const int*)d_in[5];
    const int*   user_nt = (const int*)d_in[6];
    const int*   item_h  = (const int*)d_in[7];
    const int*   item_t  = (const int*)d_in[9];
    const int*   item_nh = (const int*)d_in[10];
    const int*   item_nr = (const int*)d_in[11];
    const int*   item_nt = (const int*)d_in[12];
    const float* E       = (const float*)d_in[13];
    const float* R       = (const float*)d_in[14];
    const float* W       = (const float*)d_in[15];
    const float* a       = (const float*)d_in[16];
    float* out = (float*)d_out;

    const int B = in_sizes[0];
    int L = in_sizes[1] / (B * TT);
    if (L < 1) L = 1;

    ckgat_fused<<<B, 256>>>(items, user_h, user_t, user_nh, user_nr, user_nt,
                            item_h, item_t, item_nh, item_nr, item_nt,
                            E, R, W, a, out, B, L);
}